// round 17
// baseline (speedup 1.0000x reference)
#include <cuda_runtime.h>
#include <cstdint>
#include <math.h>

#define LSTMN 256
#define CLSZ  16
#define NTH   256
#define NBLK  6

struct __align__(16) Smem {
    float wih[64 * 256];   // 64 KB: own gate rows (gate q, elems [16r,16r+16))
    float whh[64 * 256];   // 64 KB
    float w1c[256 * 16];   // 16 KB: w1 columns [rank*16, rank*16+16)
    float w2c[256 * 16];   // 16 KB: w2 columns
    float h[2][256];       // double-buffered replicated h
    float v[256];
    float gxc[6][64];      // gx cache: 0=enc0, 1=zero(anchors 0/1), 2..5=anchors
    float gtmp[64];        // whh @ h, precomputed under the sample barrier
    float g[64], bsum[64];
    float hseg[16], c16[16];
    float pw1[256];        // column partial of w1 @ h
    float pw2[256];        // column partial of w2 @ h
    float my_aw1[128];     // (layer,half) CTA's gathered anchors_w1 slice
    float red[16];         // [0..11] logit partials (2/layer); [12..15] scratch
    float gum[8];
    float lp, ent;
    int   idx;
};

__device__ float g_lp[NBLK];
__device__ float g_ent[NBLK];
__device__ int   g_count;

// ---------------- low-level helpers ----------------

__device__ __forceinline__ uint32_t sm_u32(const void* p) {
    return (uint32_t)__cvta_generic_to_shared(p);
}
__device__ __forceinline__ uint32_t ctarank() {
    uint32_t r; asm("mov.u32 %0, %%cluster_ctarank;" : "=r"(r)); return r;
}
__device__ __forceinline__ float ds_ld(uint32_t laddr, uint32_t rank) {
    uint32_t ra; float val;
    asm volatile("mapa.shared::cluster.u32 %0, %1, %2;" : "=r"(ra) : "r"(laddr), "r"(rank));
    asm volatile("ld.shared::cluster.f32 %0, [%1];" : "=f"(val) : "r"(ra));
    return val;
}
__device__ __forceinline__ void ds_st(uint32_t laddr, uint32_t rank, float val) {
    uint32_t ra;
    asm volatile("mapa.shared::cluster.u32 %0, %1, %2;" : "=r"(ra) : "r"(laddr), "r"(rank));
    asm volatile("st.shared::cluster.f32 [%0], %1;" :: "r"(ra), "f"(val) : "memory");
}
__device__ __forceinline__ void csync() {
    asm volatile("barrier.cluster.arrive.aligned;" ::: "memory");
    asm volatile("barrier.cluster.wait.aligned;" ::: "memory");
}
__device__ __forceinline__ void carrive() {
    asm volatile("barrier.cluster.arrive.aligned;" ::: "memory");
}
__device__ __forceinline__ void cwait() {
    asm volatile("barrier.cluster.wait.aligned;" ::: "memory");
}

// threefry2x32, 20 rounds — exact JAX semantics
__device__ __forceinline__ uint2 tf2x32(uint2 key, uint2 ctr) {
    uint32_t ks0 = key.x, ks1 = key.y, ks2 = ks0 ^ ks1 ^ 0x1BD11BDAu;
    uint32_t x0 = ctr.x + ks0, x1 = ctr.y + ks1;
#define TF_RND(r) { x0 += x1; x1 = (x1 << (r)) | (x1 >> (32 - (r))); x1 ^= x0; }
    TF_RND(13) TF_RND(15) TF_RND(26) TF_RND(6)  x0 += ks1; x1 += ks2 + 1u;
    TF_RND(17) TF_RND(29) TF_RND(16) TF_RND(24) x0 += ks2; x1 += ks0 + 2u;
    TF_RND(13) TF_RND(15) TF_RND(26) TF_RND(6)  x0 += ks0; x1 += ks1 + 3u;
    TF_RND(17) TF_RND(29) TF_RND(16) TF_RND(24) x0 += ks1; x1 += ks2 + 4u;
    TF_RND(13) TF_RND(15) TF_RND(26) TF_RND(6)  x0 += ks2; x1 += ks0 + 5u;
#undef TF_RND
    return make_uint2(x0, x1);
}

// fast MUFU-path tanh/sigmoid (R10/R12/R16-proven; err ~1e-6 vs 1e-3 tolerance)
__device__ __forceinline__ float my_tanh(float xv) {
    float ax = fabsf(xv);
    float t = __expf(-2.0f * ax);
    float r = (1.0f - t) / (1.0f + t);
    return copysignf(r, xv);
}
__device__ __forceinline__ float my_sig(float xv) {
    return 1.0f / (1.0f + __expf(-xv));
}

// 64-row matvec: dst[r] = W[r,:] @ hv  (8 warps x 8 rows)
__device__ __forceinline__ void mv64(const float* W, const float* hv, float* dst, int tid) {
    const int lane = tid & 31, wrp = tid >> 5;
    const float4* HV = (const float4*)hv;
    float4 ha = HV[lane], hb = HV[lane + 32];
#pragma unroll
    for (int rr = 0; rr < 8; rr++) {
        int r = wrp * 8 + rr;
        const float4* wh = (const float4*)(W + r * LSTMN);
        float4 a = wh[lane], b4 = wh[lane + 32];
        float acc = a.x * ha.x + a.y * ha.y + a.z * ha.z + a.w * ha.w
                  + b4.x * hb.x + b4.y * hb.y + b4.z * hb.z + b4.w * hb.w;
        acc += __shfl_xor_sync(0xffffffffu, acc, 16);
        acc += __shfl_xor_sync(0xffffffffu, acc, 8);
        acc += __shfl_xor_sync(0xffffffffu, acc, 4);
        acc += __shfl_xor_sync(0xffffffffu, acc, 2);
        acc += __shfl_xor_sync(0xffffffffu, acc, 1);
        if (lane == 0) dst[r] = acc;
    }
}

// ---------------- one LSTM cell ----------------
// mode 0: sample cell (pw2) | 1: anchor cell (pw1) | 2: final (local only)
// gmode 0: inline whh@h[hb] matvec | 1: use precomputed gtmp | 2: h == 0
__device__ __forceinline__ void do_cell(Smem* s, int rank, int tid, int mode,
                                        int xs, int gmode, int hb) {
    __syncthreads();
    if (gmode == 2) {
        if (tid < 64) s->g[tid] = s->gxc[xs][tid] + s->bsum[tid];
    } else if (gmode == 1) {
        if (tid < 64) s->g[tid] = s->gtmp[tid] + s->gxc[xs][tid] + s->bsum[tid];
    } else {
        const int lane = tid & 31, wrp = tid >> 5;
        const float4* HV = (const float4*)s->h[hb];
        float4 ha = HV[lane], hbv = HV[lane + 32];
#pragma unroll
        for (int rr = 0; rr < 8; rr++) {
            int r = wrp * 8 + rr;
            const float4* wh = (const float4*)(s->whh + r * LSTMN);
            float4 a = wh[lane], b4 = wh[lane + 32];
            float acc = a.x * ha.x + a.y * ha.y + a.z * ha.z + a.w * ha.w
                      + b4.x * hbv.x + b4.y * hbv.y + b4.z * hbv.z + b4.w * hbv.w;
            acc += __shfl_xor_sync(0xffffffffu, acc, 16);
            acc += __shfl_xor_sync(0xffffffffu, acc, 8);
            acc += __shfl_xor_sync(0xffffffffu, acc, 4);
            acc += __shfl_xor_sync(0xffffffffu, acc, 2);
            acc += __shfl_xor_sync(0xffffffffu, acc, 1);
            if (lane == 0) s->g[r] = acc + s->gxc[xs][r] + s->bsum[r];
        }
    }
    __syncthreads();

    // H phase: local (own 16 elements); push new h into buffer hb^1
    if (tid < 16) {
        int j = tid;
        float gi = s->g[j], gf = s->g[16 + j], gg = s->g[32 + j], go = s->g[48 + j];
        float cn = my_sig(gf) * s->c16[j] + my_sig(gi) * my_tanh(gg);
        float hn = my_sig(go) * my_tanh(cn);
        s->c16[j] = cn;
        s->hseg[j] = hn;
        if (mode != 2) {
            uint32_t ha = sm_u32(&s->h[hb ^ 1][rank * 16 + j]);
#pragma unroll
            for (int r = 0; r < CLSZ; r++) ds_st(ha, (uint32_t)r, hn);
        }
    }
    __syncthreads();

    if (mode != 2) {
        // local column-partial matvec over own h segment
        const float* wc = (mode == 1 ? s->w1c : s->w2c) + tid * 16;
        float acc = 0.0f;
#pragma unroll
        for (int k = 0; k < 16; k++) acc = fmaf(wc[k], s->hseg[k], acc);
        if (mode == 1) s->pw1[tid] = acc; else s->pw2[tid] = acc;
        csync();   // h broadcast + partials visible cluster-wide
    }
}

// gather summed anchors_w1 slice for (layer l, half) CTAs serving slot
__device__ __forceinline__ void do_anchor_gather(Smem* s, int rank, int tid, int slot) {
    int half = rank >> 3, l = rank & 7;
    bool gat = (l == slot) || (slot == 0 && l == 1);
    if (gat && tid < 128) {
        uint32_t pa = sm_u32(&s->pw1[half * 128 + tid]);
        float a = 0.0f;
#pragma unroll
        for (int r = 0; r < CLSZ; r++) a += ds_ld(pa, (uint32_t)r);
        s->my_aw1[tid] = a;
    }
}

// ---------------- sampling: logits round overlapped with gtmp matvec ------------
__device__ __forceinline__ void do_sample(Smem* s, int rank, int tid, int layer,
                                          uint2 bkey, int step, float* out, int b,
                                          int hb) {
    const int lane = tid & 31, wrp = tid >> 5;
    const int half = rank >> 3, l = rank & 7;

    // qv: CTA (l,half) pulls pw2 and computes its half of layer-l's logit
    if (l < layer && tid < 128) {
        uint32_t pa = sm_u32(&s->pw2[half * 128 + tid]);
        float a = 0.0f;
#pragma unroll
        for (int r = 0; r < CLSZ; r++) a += ds_ld(pa, (uint32_t)r);
        int e = half * 128 + tid;
        float val = my_tanh(s->my_aw1[tid] + a) * s->v[e];
        val += __shfl_xor_sync(0xffffffffu, val, 16);
        val += __shfl_xor_sync(0xffffffffu, val, 8);
        val += __shfl_xor_sync(0xffffffffu, val, 4);
        val += __shfl_xor_sync(0xffffffffu, val, 2);
        val += __shfl_xor_sync(0xffffffffu, val, 1);
        if (lane == 0) s->red[12 + wrp] = val;
    } else if (tid >= 224) {
        // warp 7 (idle in qv): Gumbel precompute — accurate logf (index fidelity)
        int gl = tid - 224;
        if (gl < layer) {
            uint2 skey = tf2x32(bkey, make_uint2(0u, (uint32_t)step));
            uint2 o = tf2x32(skey, make_uint2(0u, (uint32_t)gl));
            uint32_t bits = o.x ^ o.y;
            float u = __uint_as_float((bits >> 9) | 0x3f800000u) - 1.0f;
            const float TINYF = 1.17549435e-38f;
            float up = fmaxf(TINYF, u + TINYF);
            s->gum[gl] = -logf(-logf(up));
        }
    }
    __syncthreads();
    if (l < layer && tid == 0) {
        float p = s->red[12] + s->red[13] + s->red[14] + s->red[15];
        uint32_t ra = sm_u32(&s->red[2 * l + half]);
#pragma unroll
        for (int r = 0; r < CLSZ; r++) ds_st(ra, (uint32_t)r, p);
    }
    __syncthreads();
    // split barrier: overlap the NEXT cell's recurrent matvec with the round.
    // h[hb] was published a full round ago (stable); gtmp is local.
    carrive();
    mv64(s->whh, s->h[hb], s->gtmp, tid);
    cwait();

    // warp 0: logits + Gumbel argmax (replicated per CTA)
    if (tid < 32) {
        const bool act = lane < layer;
        float logit = 0.0f;
        if (act)
            logit = 1.1f * my_tanh((s->red[2 * lane] + s->red[2 * lane + 1]) * 0.2f);
        float pert = act ? (s->gum[lane] + logit) : -1e38f;
        float bp = pert; int bi = act ? lane : 64;
#pragma unroll
        for (int off = 16; off; off >>= 1) {
            float op = __shfl_xor_sync(0xffffffffu, bp, off);
            int oi = __shfl_xor_sync(0xffffffffu, bi, off);
            if (op > bp || (op == bp && oi < bi)) { bp = op; bi = oi; }
        }
        float lm = act ? logit : -1e38f;
#pragma unroll
        for (int off = 16; off; off >>= 1)
            lm = fmaxf(lm, __shfl_xor_sync(0xffffffffu, lm, off));
        float se = act ? __expf(logit - lm) : 0.0f;
#pragma unroll
        for (int off = 16; off; off >>= 1)
            se += __shfl_xor_sync(0xffffffffu, se, off);
        float lse = __logf(se);
        float ls = logit - lm - lse;
        float ls_best = __shfl_sync(0xffffffffu, ls, bi);
        float ec = act ? (-ls * __expf(ls)) : 0.0f;
#pragma unroll
        for (int off = 16; off; off >>= 1)
            ec += __shfl_xor_sync(0xffffffffu, ec, off);
        if (lane == 0) {
            s->lp += -ls_best;
            s->ent += ec;
            s->idx = bi;
            if (rank == 0) out[b * 10 + step] = (float)bi;
        }
    }
    __syncthreads();   // idx + gtmp visible to all
}

// ---------------- main kernel: one 16-CTA cluster per block ----------------
__global__ void __launch_bounds__(NTH, 1) ctrl_kernel(
    const float* __restrict__ enc_w, const float* __restrict__ w_ih,
    const float* __restrict__ w_hh, const float* __restrict__ b_ih,
    const float* __restrict__ b_hh, const float* __restrict__ w1,
    const float* __restrict__ w2, const float* __restrict__ v,
    float* __restrict__ out)
{
    extern __shared__ char smraw[];
    Smem* s = (Smem*)smraw;
    const int tid = threadIdx.x;
    const int rank = (int)ctarank();
    const int b = blockIdx.y;

    // ---- prologue (R16 verbatim) ----
    {
        for (int i = tid; i < 64 * 64; i += NTH) {
            int lr = i >> 6, pos = i & 63;
            int grow = ((lr >> 4) << 8) + rank * 16 + (lr & 15);
            ((float4*)s->wih)[i] = ((const float4*)w_ih)[grow * 64 + pos];
        }
        for (int i = tid; i < 64 * 64; i += NTH) {
            int lr = i >> 6, pos = i & 63;
            int grow = ((lr >> 4) << 8) + rank * 16 + (lr & 15);
            ((float4*)s->whh)[i] = ((const float4*)w_hh)[grow * 64 + pos];
        }
        {
            int j = tid;
            const float4* s1 = (const float4*)(w1 + j * 256 + rank * 16);
            const float4* s2 = (const float4*)(w2 + j * 256 + rank * 16);
            float4* d1 = (float4*)(s->w1c + j * 16);
            float4* d2 = (float4*)(s->w2c + j * 16);
#pragma unroll
            for (int k = 0; k < 4; k++) { d1[k] = s1[k]; d2[k] = s2[k]; }
        }
        if (tid < 64) {
            int grow = ((tid >> 4) << 8) + rank * 16 + (tid & 15);
            s->bsum[tid] = b_ih[grow] + b_hh[grow];
            s->gxc[1][tid] = 0.0f;   // anchors 0/1 are zero vectors
        }
        s->v[tid] = v[tid];
        s->h[0][tid] = enc_w[tid];   // temp: enc0 as matvec input
        if (tid < 16) s->c16[tid] = 0.0f;
        if (tid == 0) { s->lp = 0.0f; s->ent = 0.0f; s->idx = 0; }
    }
    __syncthreads();
    mv64(s->wih, s->h[0], s->gxc[0], tid);   // gxc[0] = wih @ enc0
    csync();   // enc0 reads done everywhere before Z-cell pushes overwrite h[0]

    const uint2 key42 = make_uint2(0u, 42u);
    const uint2 bkey = tf2x32(key42, make_uint2(0u, (uint32_t)b));

    // Z cell (zero state, input enc0): pushes h1 -> h[0]
    int hb = 1;
    do_cell(s, rank, tid, 1, 0, 2, hb);
    hb = 0;                              // h1 in h[0]
    do_anchor_gather(s, rank, tid, 0);   // aw1 slices for layers 0 & 1

    int step = 0;
#pragma unroll 1
    for (int layer = 2; layer <= 6; layer++) {
        // two sample cells: BOTH followed by a sample (10 samples total)
#pragma unroll 1
        for (int rep = 0; rep < 2; rep++) {
            int xs = (rep == 0) ? 0 : ((s->idx < 2) ? 1 : s->idx);
            // rep0: inline matvec (follows anchor round, no gtmp available)
            // rep1: gtmp precomputed under the previous sample's barrier
            do_cell(s, rank, tid, 0, xs, (rep == 0) ? 0 : 1, hb);
            hb ^= 1;
            do_sample(s, rank, tid, layer, bkey, step, out, b, hb);
            step++;
        }
        // layer-final anchor cell (input anchors[idx of sample 2]); gtmp ready
        int xs = (s->idx < 2) ? 1 : s->idx;
        if (layer < 6) {
            do_cell(s, rank, tid, 1, xs, 1, hb);
            hb ^= 1;
            do_anchor_gather(s, rank, tid, layer);
            mv64(s->wih, s->h[hb], s->gxc[layer], tid);  // gx cache of new anchor
            __syncthreads();
        } else {
            do_cell(s, rank, tid, 2, xs, 1, hb);         // final: local c,h only
        }
    }

    // ---- epilogue: deadlock-free last-cluster scalar reduction ----
    if (rank == 0 && tid == 0) {
        g_lp[b] = s->lp;
        g_ent[b] = s->ent;
        __threadfence();
        int prev = atomicAdd(&g_count, 1);
        if (prev == NBLK - 1) {
            __threadfence();
            float slp = 0.0f, sent = 0.0f;
#pragma unroll
            for (int bb = 0; bb < NBLK; bb++) {
                slp += ((volatile float*)g_lp)[bb];
                sent += ((volatile float*)g_ent)[bb];
            }
            out[60] = slp;
            out[61] = sent;
            g_count = 0;   // reset for graph replay
        }
    }
    __syncthreads();
    if (b == NBLK - 1 && tid < 16) {
        out[62 + rank * 16 + tid] = s->c16[tid];
        out[62 + 256 + rank * 16 + tid] = s->hseg[tid];
    }
}

extern "C" void kernel_launch(void* const* d_in, const int* in_sizes, int n_in,
                              void* d_out, int out_size) {
    const float* enc_w = (const float*)d_in[0];
    const float* w_ih  = (const float*)d_in[1];
    const float* w_hh  = (const float*)d_in[2];
    const float* b_ih  = (const float*)d_in[3];
    const float* b_hh  = (const float*)d_in[4];
    const float* w1    = (const float*)d_in[5];
    const float* w2    = (const float*)d_in[6];
    const float* v     = (const float*)d_in[7];
    float* out = (float*)d_out;

    cudaFuncSetAttribute(ctrl_kernel,
                         cudaFuncAttributeMaxDynamicSharedMemorySize,
                         (int)sizeof(Smem));
    cudaFuncSetAttribute(ctrl_kernel,
                         cudaFuncAttributeNonPortableClusterSizeAllowed, 1);

    cudaLaunchConfig_t cfg = {};
    cfg.gridDim = dim3(CLSZ, NBLK, 1);
    cfg.blockDim = dim3(NTH, 1, 1);
    cfg.dynamicSmemBytes = sizeof(Smem);
    cfg.stream = 0;
    cudaLaunchAttribute at[1];
    at[0].id = cudaLaunchAttributeClusterDimension;
    at[0].val.clusterDim.x = CLSZ;
    at[0].val.clusterDim.y = 1;
    at[0].val.clusterDim.z = 1;
    cfg.attrs = at;
    cfg.numAttrs = 1;

    cudaLaunchKernelEx(&cfg, ctrl_kernel,
                       enc_w, w_ih, w_hh, b_ih, b_hh, w1, w2, v, out);
}